// round 12
// baseline (speedup 1.0000x reference)
#include <cuda_runtime.h>
#include <cstdint>

#define BB 64
#define NN 64
#define TT 16
#define DD 512
#define RR (BB*NN)          // 4096 rows (b,m)
#define THR2 (150.0f*150.0f)

// ---------------- scratch (device globals, no allocation) ----------------
__device__ float g_agg[RR*DD];      // aggregation output  [r][c]
__device__ float g_z[RR*DD];        // pre-BN GEMM output  [r][o]
__device__ float g_psum[64*DD];     // BN partial sums   [rTile][col]
__device__ float g_psq[64*DD];      // BN partial sumsq  [rTile][col]
__device__ float g_scale[DD];
__device__ float g_shift[DD];

// ---------------- warmup (forces stream resource materialization pre-main) --
__global__ void k_warm() {}

// ---------------- side-stream copy: out[:, :, t!=15, :] = pf ----------------
__global__ void __launch_bounds__(256) k_copy15(const float4* __restrict__ src,
                                                float4* __restrict__ dst) {
    int t  = threadIdx.x;
    int tt = blockIdx.y;          // 0..14
    int rb = blockIdx.x;          // 0..63
    #pragma unroll 4
    for (int j = t; j < 64*128; j += 256) {
        int k = j >> 7, w = j & 127;
        size_t idx = ((size_t)(rb*64 + k)*16 + tt) * 128 + w;
        dst[idx] = src[idx];
    }
}

// ---------------- graph aggregation (adjacency fused) ----------------
__global__ void __launch_bounds__(256) k_agg(const float* __restrict__ pf,
                                             const float* __restrict__ bbx, int mode) {
    __shared__ float Asm[NN*NN];
    __shared__ float Xs[NN][68];
    __shared__ float cx[NN], cy[NN], invdeg[NN];
    int b = blockIdx.x;
    int cBase = blockIdx.y * 64;
    int t = threadIdx.x;

    if (t < NN) {
        const float* p = bbx + (b*NN + t)*4;
        cx[t] = p[0] + 0.5f*p[2];
        cy[t] = p[1] + 0.5f*p[3];
    }
    __syncthreads();
    if (t < NN) {
        float x0 = cx[t], y0 = cy[t];
        int cnt = 0;
        #pragma unroll 8
        for (int m = 0; m < NN; m++) {
            float dx = x0 - cx[m], dy = y0 - cy[m];
            if (m != t && dx*dx + dy*dy < THR2) cnt++;
        }
        invdeg[t] = 1.0f / ((float)(cnt + 1) + 1e-6f);
    }
    __syncthreads();
    #pragma unroll
    for (int i = 0; i < 16; i++) {
        int e = t + 256*i;
        int m = e >> 6, n = e & 63;
        float dx = cx[n]-cx[m], dy = cy[n]-cy[m];
        float d2 = dx*dx + dy*dy;
        Asm[e] = (n == m || d2 < THR2) ? invdeg[n] : 0.0f;
    }
    #pragma unroll
    for (int i = 0; i < 4; i++) {
        int e  = t + 256*i;
        int n  = e >> 4;
        int cg = (e & 15) * 4;
        float4 v;
        if (mode == 0) {
            v = *(const float4*)&pf[((b*NN + n)*TT + 15)*DD + cBase + cg];
        } else {
            float4 z  = *(const float4*)&g_z[(b*NN + n)*DD + cBase + cg];
            float4 sc = *(const float4*)&g_scale[cBase + cg];
            float4 sh = *(const float4*)&g_shift[cBase + cg];
            v.x = fmaxf(fmaf(z.x, sc.x, sh.x), 0.0f);
            v.y = fmaxf(fmaf(z.y, sc.y, sh.y), 0.0f);
            v.z = fmaxf(fmaf(z.z, sc.z, sh.z), 0.0f);
            v.w = fmaxf(fmaf(z.w, sc.w, sh.w), 0.0f);
        }
        *(float4*)&Xs[n][cg] = v;
    }
    __syncthreads();

    int ty = t >> 4, tx = t & 15;
    int m0 = ty * 4, c0 = tx * 4;
    float acc[4][4] = {};
    for (int n = 0; n < NN; n++) {
        float a0 = Asm[(m0+0)*NN + n];
        float a1 = Asm[(m0+1)*NN + n];
        float a2 = Asm[(m0+2)*NN + n];
        float a3 = Asm[(m0+3)*NN + n];
        float4 xv = *(const float4*)&Xs[n][c0];
        acc[0][0] += a0*xv.x; acc[0][1] += a0*xv.y; acc[0][2] += a0*xv.z; acc[0][3] += a0*xv.w;
        acc[1][0] += a1*xv.x; acc[1][1] += a1*xv.y; acc[1][2] += a1*xv.z; acc[1][3] += a1*xv.w;
        acc[2][0] += a2*xv.x; acc[2][1] += a2*xv.y; acc[2][2] += a2*xv.z; acc[2][3] += a2*xv.w;
        acc[3][0] += a3*xv.x; acc[3][1] += a3*xv.y; acc[3][2] += a3*xv.z; acc[3][3] += a3*xv.w;
    }
    #pragma unroll
    for (int i = 0; i < 4; i++) {
        float4 v = make_float4(acc[i][0], acc[i][1], acc[i][2], acc[i][3]);
        *(float4*)&g_agg[(b*NN + m0 + i)*DD + cBase + c0] = v;
    }
}

// ---------------- tf32 mma.sync GEMM + fused BN partial stats ----------------
// g_z[r][o] = sum_c g_agg[r][c]*W[o][c] + bias[o]
// Block 64x64, BK=32, 4 warps (2M x 2N), warp tile 32x32 via m16n8k8.
// Smem: K-major stride 36, THREE pipeline stages filled by cp.async.
#define LDK 36
#define STGF 4608                  // floats per stage (A 2304 + B 2304)
#define ABUF(s) ((s)*STGF)
#define BBUF(s) ((s)*STGF + 2304)
#define GEMM_SMEM (3*STGF*4)       // 54KB

__device__ __forceinline__ void mma_tf32(float* c, const uint32_t* a, const uint32_t* b) {
    asm volatile(
        "mma.sync.aligned.m16n8k8.row.col.f32.tf32.tf32.f32 "
        "{%0,%1,%2,%3}, {%4,%5,%6,%7}, {%8,%9}, {%0,%1,%2,%3};"
        : "+f"(c[0]), "+f"(c[1]), "+f"(c[2]), "+f"(c[3])
        : "r"(a[0]), "r"(a[1]), "r"(a[2]), "r"(a[3]), "r"(b[0]), "r"(b[1]));
}
__device__ __forceinline__ void cp16(uint32_t dst, const void* src) {
    asm volatile("cp.async.ca.shared.global [%0], [%1], 16;" :: "r"(dst), "l"(src));
}
#define CP_COMMIT() asm volatile("cp.async.commit_group;" ::: "memory")
#define CP_WAIT(n)  asm volatile("cp.async.wait_group %0;" :: "n"(n) : "memory")

// fill one stage with chunk k0 (all 128 threads): A 64x32 + B 64x32 floats
__device__ __forceinline__ void fill_stage(uint32_t sbase, int stg, int k0,
                                           const float* A, const float* W,
                                           int rBase, int oBase, int frow, int fcg) {
    #pragma unroll
    for (int i = 0; i < 4; i++) {
        int row = frow + 16*i;
        cp16(sbase + (ABUF(stg) + row*LDK + fcg)*4, &A[(rBase+row)*DD + k0 + fcg]);
    }
    #pragma unroll
    for (int i = 0; i < 4; i++) {
        int row = frow + 16*i;
        cp16(sbase + (BBUF(stg) + row*LDK + fcg)*4, &W[(oBase+row)*DD + k0 + fcg]);
    }
    CP_COMMIT();
}

__global__ void __launch_bounds__(128, 4) k_gemm_mma(const float* __restrict__ W,
                                                     const float* __restrict__ bias) {
    extern __shared__ float sm[];
    uint32_t sbase = (uint32_t)__cvta_generic_to_shared(sm);
    int t = threadIdx.x;
    int lane = t & 31;
    int wid = t >> 5;                       // 0..3
    int wm = wid >> 1, wn = wid & 1;        // 2x2 warps, each 32x32
    int rBase = blockIdx.x * 64;
    int oBase = blockIdx.y * 64;
    const float* A = g_agg;

    // fill indexing: 512 float4 per operand, 128 threads -> 4 each
    int frow = t >> 3, fcg = (t & 7) * 4;   // frow 0..15 (+16 stride)

    // fragment base offsets (floats) within a stage
    int aBase = (wm*32 + (lane >> 2))*LDK + (lane & 3);
    int bBase = (wn*32 + (lane >> 2))*LDK + (lane & 3);

    float acc[2][4][4];
    #pragma unroll
    for (int mt = 0; mt < 2; mt++)
        #pragma unroll
        for (int nt = 0; nt < 4; nt++)
            #pragma unroll
            for (int j = 0; j < 4; j++) acc[mt][nt][j] = 0.0f;

    // ---- prologue: fill stages 0,1 with chunks 0,1 ----
    fill_stage(sbase, 0, 0,  A, W, rBase, oBase, frow, fcg);
    fill_stage(sbase, 1, 32, A, W, rBase, oBase, frow, fcg);

    int stg = 0;
    #pragma unroll 1
    for (int it = 0; it < 16; it++) {
        if (it + 2 < 16)
            fill_stage(sbase, (stg + 2 >= 3 ? stg - 1 : stg + 2), (it + 2) * 32,
                       A, W, rBase, oBase, frow, fcg);
        // need chunk `it` landed; newer groups allowed in flight:
        if (it < 14)      CP_WAIT(2);
        else if (it < 15) CP_WAIT(1);
        else              CP_WAIT(0);
        __syncthreads();

        const float* as = &sm[ABUF(stg) + aBase];
        const float* bs = &sm[BBUF(stg) + bBase];
        #pragma unroll
        for (int ks = 0; ks < 4; ks++) {
            uint32_t af[2][4], bf[4][2];
            #pragma unroll
            for (int mt = 0; mt < 2; mt++) {
                #pragma unroll
                for (int j = 0; j < 4; j++)
                    af[mt][j] = __float_as_uint(as[(mt*16 + 8*(j&1))*LDK + ks*8 + 4*(j>>1)]);
            }
            #pragma unroll
            for (int nt = 0; nt < 4; nt++) {
                #pragma unroll
                for (int j = 0; j < 2; j++)
                    bf[nt][j] = __float_as_uint(bs[(nt*8)*LDK + ks*8 + 4*j]);
            }
            #pragma unroll
            for (int mt = 0; mt < 2; mt++)
                #pragma unroll
                for (int nt = 0; nt < 4; nt++)
                    mma_tf32(acc[mt][nt], af[mt], bf[nt]);
        }
        __syncthreads();   // stage may be overwritten next iteration
        stg = (stg + 1 >= 3) ? 0 : stg + 1;
    }

    // ---- epilogue: bias add, write g_z, accumulate per-column stats ----
    float s[4][2], q[4][2];
    #pragma unroll
    for (int nt = 0; nt < 4; nt++) { s[nt][0]=s[nt][1]=q[nt][0]=q[nt][1]=0.0f; }

    #pragma unroll
    for (int nt = 0; nt < 4; nt++) {
        int col = oBase + wn*32 + nt*8 + (lane & 3)*2;
        float2 bv = *(const float2*)&bias[col];
        #pragma unroll
        for (int mt = 0; mt < 2; mt++) {
            int row0 = rBase + wm*32 + mt*16 + (lane >> 2);
            float2 v0 = make_float2(acc[mt][nt][0] + bv.x, acc[mt][nt][1] + bv.y);
            float2 v1 = make_float2(acc[mt][nt][2] + bv.x, acc[mt][nt][3] + bv.y);
            *(float2*)&g_z[row0*DD + col]     = v0;
            *(float2*)&g_z[(row0+8)*DD + col] = v1;
            s[nt][0] += v0.x + v1.x;  s[nt][1] += v0.y + v1.y;
            q[nt][0] += v0.x*v0.x + v1.x*v1.x;
            q[nt][1] += v0.y*v0.y + v1.y*v1.y;
        }
    }
    #pragma unroll
    for (int off = 4; off < 32; off <<= 1) {
        #pragma unroll
        for (int nt = 0; nt < 4; nt++) {
            s[nt][0] += __shfl_xor_sync(0xffffffffu, s[nt][0], off);
            s[nt][1] += __shfl_xor_sync(0xffffffffu, s[nt][1], off);
            q[nt][0] += __shfl_xor_sync(0xffffffffu, q[nt][0], off);
            q[nt][1] += __shfl_xor_sync(0xffffffffu, q[nt][1], off);
        }
    }
    // combine across the two wm warps: red[wm][64] sums, red[128 + wm*64 + .] sqs
    float* red = sm;
    __syncthreads();
    if (lane < 4) {
        #pragma unroll
        for (int nt = 0; nt < 4; nt++) {
            int coll = wn*32 + nt*8 + lane*2;
            red[wm*64 +        coll    ] = s[nt][0];
            red[wm*64 +        coll + 1] = s[nt][1];
            red[128 + wm*64 +  coll    ] = q[nt][0];
            red[128 + wm*64 +  coll + 1] = q[nt][1];
        }
    }
    __syncthreads();
    if (t < 64) {
        float st = red[t]       + red[64 + t];
        float qt = red[128 + t] + red[192 + t];
        g_psum[blockIdx.x*DD + oBase + t] = st;
        g_psq [blockIdx.x*DD + oBase + t] = qt;
    }
}

// ---------------- BN finalize ----------------
__global__ void k_finalize(const float* __restrict__ gma, const float* __restrict__ bta) {
    int o = threadIdx.x;
    float s = 0.0f, q = 0.0f;
    #pragma unroll 8
    for (int i = 0; i < 64; i++) { s += g_psum[i*DD + o]; q += g_psq[i*DD + o]; }
    float mean = s * (1.0f/4096.0f);
    float var  = q * (1.0f/4096.0f) - mean*mean;
    float inv  = rsqrtf(var + 1e-5f);
    float sc   = gma[o] * inv;
    g_scale[o] = sc;
    g_shift[o] = bta[o] - mean * sc;
}

// ---------------- BN apply + ReLU -> out[:, :, 15, :] ----------------
__global__ void k_apply(float* __restrict__ outp) {
    int i  = blockIdx.x * blockDim.x + threadIdx.x;
    int r  = i >> 7;
    int cw = i & 127;
    float4 z  = ((const float4*)g_z)[i];
    float4 sc = ((const float4*)g_scale)[cw];
    float4 sh = ((const float4*)g_shift)[cw];
    float4 h;
    h.x = fmaxf(fmaf(z.x, sc.x, sh.x), 0.0f);
    h.y = fmaxf(fmaf(z.y, sc.y, sh.y), 0.0f);
    h.z = fmaxf(fmaf(z.z, sc.z, sh.z), 0.0f);
    h.w = fmaxf(fmaf(z.w, sc.w, sh.w), 0.0f);
    *(float4*)&outp[r*(TT*DD) + 15*DD + cw*4] = h;
}

// ---------------- side stream + events (created pre-main, no allocs in launch) --
namespace {
struct SideStream {
    cudaStream_t s;
    cudaEvent_t evFork, evJoin;
    SideStream() {
        cudaStreamCreateWithFlags(&s, cudaStreamNonBlocking);
        cudaEventCreateWithFlags(&evFork, cudaEventDisableTiming);
        cudaEventCreateWithFlags(&evJoin, cudaEventDisableTiming);
        k_warm<<<1, 32, 0, s>>>();
        cudaStreamSynchronize(s);
    }
};
SideStream g_ss;
}

// ---------------- launcher ----------------
extern "C" void kernel_launch(void* const* d_in, const int* in_sizes, int n_in,
                              void* d_out, int out_size) {
    const float* pf  = (const float*)d_in[0];
    const float* bbx = (const float*)d_in[1];
    const float* w1  = (const float*)d_in[2];
    const float* b1  = (const float*)d_in[3];
    const float* g1  = (const float*)d_in[4];
    const float* be1 = (const float*)d_in[5];
    const float* w2  = (const float*)d_in[6];
    const float* b2  = (const float*)d_in[7];
    const float* g2  = (const float*)d_in[8];
    const float* be2 = (const float*)d_in[9];
    float* out = (float*)d_out;

    static int s_attr_done = 0;
    if (!s_attr_done) {
        cudaFuncSetAttribute(k_gemm_mma, cudaFuncAttributeMaxDynamicSharedMemorySize, GEMM_SMEM);
        s_attr_done = 1;
    }

    // fork: bulk copy of t=0..14 slices runs concurrently on the side stream
    cudaEventRecord(g_ss.evFork, 0);
    cudaStreamWaitEvent(g_ss.s, g_ss.evFork, 0);
    k_copy15<<<dim3(64, 15), 256, 0, g_ss.s>>>((const float4*)pf, (float4*)out);
    cudaEventRecord(g_ss.evJoin, g_ss.s);

    // layer 1
    k_agg<<<dim3(64, 8), 256>>>(pf, bbx, 0);
    k_gemm_mma<<<dim3(64, 8), 128, GEMM_SMEM>>>(w1, b1);
    k_finalize<<<1, 512>>>(g1, be1);

    // layer 2 (BN-apply of layer 1 fused into the aggregation load)
    k_agg<<<dim3(64, 8), 256>>>(nullptr, bbx, 1);
    k_gemm_mma<<<dim3(64, 8), 128, GEMM_SMEM>>>(w2, b2);
    k_finalize<<<1, 512>>>(g2, be2);
    k_apply<<<2048, 256>>>(out);

    // join side stream before the graph/launch completes
    cudaStreamWaitEvent(0, g_ss.evJoin, 0);
}

// round 13
// speedup vs baseline: 1.1421x; 1.1421x over previous
#include <cuda_runtime.h>
#include <cstdint>

#define BB 64
#define NN 64
#define TT 16
#define DD 512
#define RR (BB*NN)          // 4096 rows (b,m)
#define THR2 (150.0f*150.0f)

// ---------------- scratch (device globals, no allocation) ----------------
__device__ float g_agg[RR*DD];      // aggregation output  [r][c]
__device__ float g_z[RR*DD];        // pre-BN GEMM output  [r][o]
__device__ float g_psum[64*DD];     // BN partial sums   [rTile][col]
__device__ float g_psq[64*DD];      // BN partial sumsq  [rTile][col]
__device__ float g_scale[DD];
__device__ float g_shift[DD];

// ---------------- warmup (forces stream resource materialization pre-main) --
__global__ void k_warm() {}

// ---------------- side-stream copy: out[:, :, t!=15, :] = pf ----------------
__global__ void __launch_bounds__(256) k_copy15(const float4* __restrict__ src,
                                                float4* __restrict__ dst) {
    int t  = threadIdx.x;
    int tt = blockIdx.y;          // 0..14
    int rb = blockIdx.x;          // 0..63
    #pragma unroll 4
    for (int j = t; j < 64*128; j += 256) {
        int k = j >> 7, w = j & 127;
        size_t idx = ((size_t)(rb*64 + k)*16 + tt) * 128 + w;
        dst[idx] = src[idx];
    }
}

// ---------------- common MMA helper ----------------
__device__ __forceinline__ void mma_tf32(float* c, const uint32_t* a, const uint32_t* b) {
    asm volatile(
        "mma.sync.aligned.m16n8k8.row.col.f32.tf32.tf32.f32 "
        "{%0,%1,%2,%3}, {%4,%5,%6,%7}, {%8,%9}, {%0,%1,%2,%3};"
        : "+f"(c[0]), "+f"(c[1]), "+f"(c[2]), "+f"(c[3])
        : "r"(a[0]), "r"(a[1]), "r"(a[2]), "r"(a[3]), "r"(b[0]), "r"(b[1]));
}
__device__ __forceinline__ void cp16(uint32_t dst, const void* src) {
    asm volatile("cp.async.ca.shared.global [%0], [%1], 16;" :: "r"(dst), "l"(src));
}
#define CP_COMMIT() asm volatile("cp.async.commit_group;" ::: "memory")
#define CP_WAIT0()  asm volatile("cp.async.wait_group 0;" ::: "memory")

// ---------------- graph aggregation via tf32 MMA (adjacency fused) ----------------
// Per block (batch b, 64-col chunk): g_agg[b][m][c] = sum_n Asm[m][n] * X[n][c]
// Asm[m][n] = Anorm[n][m] built in-smem from bboxes.
// mode 0: X[n][c] = pf[b][n][15][c] ; mode 1: X = relu(g_z*scale + shift)
#define AGG_LD 68
__global__ void __launch_bounds__(128) k_agg(const float* __restrict__ pf,
                                             const float* __restrict__ bbx, int mode) {
    __shared__ float Asm[NN*AGG_LD];    // [m][n] stride 68
    __shared__ float Xs[NN*AGG_LD];     // [n][c] stride 68
    __shared__ float cx[NN], cy[NN], invdeg[NN];
    int b = blockIdx.x;
    int cBase = blockIdx.y * 64;
    int t = threadIdx.x;
    int lane = t & 31, wid = t >> 5;
    int wm = wid >> 1, wn = wid & 1;     // 2x2 warps: 32 rows x 32 cols each

    if (t < NN) {
        const float* p = bbx + (b*NN + t)*4;
        cx[t] = p[0] + 0.5f*p[2];
        cy[t] = p[1] + 0.5f*p[3];
    }
    __syncthreads();
    if (t < NN) {
        float x0 = cx[t], y0 = cy[t];
        int cnt = 0;
        #pragma unroll 8
        for (int m = 0; m < NN; m++) {
            float dx = x0 - cx[m], dy = y0 - cy[m];
            if (m != t && dx*dx + dy*dy < THR2) cnt++;
        }
        invdeg[t] = 1.0f / ((float)(cnt + 1) + 1e-6f);
    }
    __syncthreads();
    // adjacency: 4096 entries, 32 per thread
    #pragma unroll
    for (int i = 0; i < 32; i++) {
        int e = t + 128*i;
        int m = e >> 6, n = e & 63;
        float dx = cx[n]-cx[m], dy = cy[n]-cy[m];
        float d2 = dx*dx + dy*dy;
        Asm[m*AGG_LD + n] = (n == m || d2 < THR2) ? invdeg[n] : 0.0f;
    }
    // X fill: 64 rows x 64 cols = 1024 float4, 8 per thread
    #pragma unroll
    for (int i = 0; i < 8; i++) {
        int e  = t + 128*i;          // 0..1023
        int n  = e >> 4;
        int cg = (e & 15) * 4;
        float4 v;
        if (mode == 0) {
            v = *(const float4*)&pf[((b*NN + n)*TT + 15)*DD + cBase + cg];
        } else {
            float4 z  = *(const float4*)&g_z[(b*NN + n)*DD + cBase + cg];
            float4 sc = *(const float4*)&g_scale[cBase + cg];
            float4 sh = *(const float4*)&g_shift[cBase + cg];
            v.x = fmaxf(fmaf(z.x, sc.x, sh.x), 0.0f);
            v.y = fmaxf(fmaf(z.y, sc.y, sh.y), 0.0f);
            v.z = fmaxf(fmaf(z.z, sc.z, sh.z), 0.0f);
            v.w = fmaxf(fmaf(z.w, sc.w, sh.w), 0.0f);
        }
        *(float4*)&Xs[n*AGG_LD + cg] = v;
    }
    __syncthreads();

    // MMA: D[m][c], m in wm*32+mt*16+..., c in wn*32+nt*8+...
    float acc[2][4][4];
    #pragma unroll
    for (int mt = 0; mt < 2; mt++)
        #pragma unroll
        for (int nt = 0; nt < 4; nt++)
            #pragma unroll
            for (int j = 0; j < 4; j++) acc[mt][nt][j] = 0.0f;

    int ar = wm*32 + (lane >> 2);        // a-frag row base
    int bc = wn*32 + (lane >> 2);        // b-frag col base
    #pragma unroll
    for (int ks = 0; ks < 8; ks++) {
        uint32_t af[2][4], bf[4][2];
        #pragma unroll
        for (int mt = 0; mt < 2; mt++)
            #pragma unroll
            for (int j = 0; j < 4; j++)
                af[mt][j] = __float_as_uint(
                    Asm[(ar + mt*16 + 8*(j&1))*AGG_LD + ks*8 + (lane&3) + 4*(j>>1)]);
        #pragma unroll
        for (int nt = 0; nt < 4; nt++)
            #pragma unroll
            for (int j = 0; j < 2; j++)
                bf[nt][j] = __float_as_uint(
                    Xs[(ks*8 + (lane&3) + 4*j)*AGG_LD + bc + nt*8]);
        #pragma unroll
        for (int mt = 0; mt < 2; mt++)
            #pragma unroll
            for (int nt = 0; nt < 4; nt++)
                mma_tf32(acc[mt][nt], af[mt], bf[nt]);
    }

    // write g_agg
    #pragma unroll
    for (int nt = 0; nt < 4; nt++) {
        int col = cBase + wn*32 + nt*8 + (lane & 3)*2;
        #pragma unroll
        for (int mt = 0; mt < 2; mt++) {
            int row0 = b*NN + wm*32 + mt*16 + (lane >> 2);
            *(float2*)&g_agg[row0*DD + col]     = make_float2(acc[mt][nt][0], acc[mt][nt][1]);
            *(float2*)&g_agg[(row0+8)*DD + col] = make_float2(acc[mt][nt][2], acc[mt][nt][3]);
        }
    }
}

// ---------------- tf32 mma.sync GEMM + fused BN partial stats (R11 version) ----
// Block 64x128, BK=32, 8 warps (2M x 4N), warp tile 32x32 via m16n8k8.
#define LDK 36
#define ABUF(b) ((b)*2304)
#define BBUF(b) (4608 + (b)*4608)
#define GEMM_SMEM (13824*4)     // 54KB

__global__ void __launch_bounds__(256, 3) k_gemm_mma(const float* __restrict__ W,
                                                     const float* __restrict__ bias) {
    extern __shared__ float sm[];
    uint32_t sbase = (uint32_t)__cvta_generic_to_shared(sm);
    int t = threadIdx.x;
    int lane = t & 31;
    int wid = t >> 5;
    int wm = wid >> 2, wn = wid & 3;
    int rBase = blockIdx.x * 64;
    int oBase = blockIdx.y * 128;
    const float* A = g_agg;

    int frow = t >> 3, fcg = (t & 7) * 4;
    int aBase = (wm*32 + (lane >> 2))*LDK + (lane & 3);
    int bBase = (wn*32 + (lane >> 2))*LDK + (lane & 3);

    float acc[2][4][4];
    #pragma unroll
    for (int mt = 0; mt < 2; mt++)
        #pragma unroll
        for (int nt = 0; nt < 4; nt++)
            #pragma unroll
            for (int j = 0; j < 4; j++) acc[mt][nt][j] = 0.0f;

    {
        #pragma unroll
        for (int i = 0; i < 2; i++) {
            int row = frow + 32*i;
            cp16(sbase + (ABUF(0) + row*LDK + fcg)*4, &A[(rBase+row)*DD + fcg]);
        }
        #pragma unroll
        for (int i = 0; i < 4; i++) {
            int row = frow + 32*i;
            cp16(sbase + (BBUF(0) + row*LDK + fcg)*4, &W[(oBase+row)*DD + fcg]);
        }
        CP_COMMIT();
        CP_WAIT0();
        __syncthreads();
    }

    #pragma unroll 1
    for (int it = 0; it < 16; it++) {
        int cur = it & 1;
        if (it + 1 < 16) {
            int nb = 1 - cur;
            int k0 = (it + 1) * 32;
            #pragma unroll
            for (int i = 0; i < 2; i++) {
                int row = frow + 32*i;
                cp16(sbase + (ABUF(nb) + row*LDK + fcg)*4, &A[(rBase+row)*DD + k0 + fcg]);
            }
            #pragma unroll
            for (int i = 0; i < 4; i++) {
                int row = frow + 32*i;
                cp16(sbase + (BBUF(nb) + row*LDK + fcg)*4, &W[(oBase+row)*DD + k0 + fcg]);
            }
            CP_COMMIT();
        }
        const float* as = &sm[ABUF(cur) + aBase];
        const float* bs = &sm[BBUF(cur) + bBase];
        #pragma unroll
        for (int ks = 0; ks < 4; ks++) {
            uint32_t af[2][4], bf[4][2];
            #pragma unroll
            for (int mt = 0; mt < 2; mt++) {
                #pragma unroll
                for (int j = 0; j < 4; j++)
                    af[mt][j] = __float_as_uint(as[(mt*16 + 8*(j&1))*LDK + ks*8 + 4*(j>>1)]);
            }
            #pragma unroll
            for (int nt = 0; nt < 4; nt++) {
                #pragma unroll
                for (int j = 0; j < 2; j++)
                    bf[nt][j] = __float_as_uint(bs[(nt*8)*LDK + ks*8 + 4*j]);
            }
            #pragma unroll
            for (int mt = 0; mt < 2; mt++)
                #pragma unroll
                for (int nt = 0; nt < 4; nt++)
                    mma_tf32(acc[mt][nt], af[mt], bf[nt]);
        }
        if (it + 1 < 16) CP_WAIT0();
        __syncthreads();
    }

    float s[4][2], q[4][2];
    #pragma unroll
    for (int nt = 0; nt < 4; nt++) { s[nt][0]=s[nt][1]=q[nt][0]=q[nt][1]=0.0f; }

    #pragma unroll
    for (int nt = 0; nt < 4; nt++) {
        int col = oBase + wn*32 + nt*8 + (lane & 3)*2;
        float2 bv = *(const float2*)&bias[col];
        #pragma unroll
        for (int mt = 0; mt < 2; mt++) {
            int row0 = rBase + wm*32 + mt*16 + (lane >> 2);
            float2 v0 = make_float2(acc[mt][nt][0] + bv.x, acc[mt][nt][1] + bv.y);
            float2 v1 = make_float2(acc[mt][nt][2] + bv.x, acc[mt][nt][3] + bv.y);
            *(float2*)&g_z[row0*DD + col]     = v0;
            *(float2*)&g_z[(row0+8)*DD + col] = v1;
            s[nt][0] += v0.x + v1.x;  s[nt][1] += v0.y + v1.y;
            q[nt][0] += v0.x*v0.x + v1.x*v1.x;
            q[nt][1] += v0.y*v0.y + v1.y*v1.y;
        }
    }
    #pragma unroll
    for (int off = 4; off < 32; off <<= 1) {
        #pragma unroll
        for (int nt = 0; nt < 4; nt++) {
            s[nt][0] += __shfl_xor_sync(0xffffffffu, s[nt][0], off);
            s[nt][1] += __shfl_xor_sync(0xffffffffu, s[nt][1], off);
            q[nt][0] += __shfl_xor_sync(0xffffffffu, q[nt][0], off);
            q[nt][1] += __shfl_xor_sync(0xffffffffu, q[nt][1], off);
        }
    }
    float* red = sm;
    __syncthreads();
    if (lane < 4) {
        #pragma unroll
        for (int nt = 0; nt < 4; nt++) {
            int coll = wn*32 + nt*8 + lane*2;
            red[wm*256 +       coll    ] = s[nt][0];
            red[wm*256 +       coll + 1] = s[nt][1];
            red[wm*256 + 128 + coll    ] = q[nt][0];
            red[wm*256 + 128 + coll + 1] = q[nt][1];
        }
    }
    __syncthreads();
    if (t < 128) {
        float st = red[t]       + red[256 + t];
        float qt = red[128 + t] + red[384 + t];
        g_psum[blockIdx.x*DD + oBase + t] = st;
        g_psq [blockIdx.x*DD + oBase + t] = qt;
    }
}

// ---------------- BN finalize ----------------
__global__ void k_finalize(const float* __restrict__ gma, const float* __restrict__ bta) {
    int o = threadIdx.x;
    float s = 0.0f, q = 0.0f;
    #pragma unroll 8
    for (int i = 0; i < 64; i++) { s += g_psum[i*DD + o]; q += g_psq[i*DD + o]; }
    float mean = s * (1.0f/4096.0f);
    float var  = q * (1.0f/4096.0f) - mean*mean;
    float inv  = rsqrtf(var + 1e-5f);
    float sc   = gma[o] * inv;
    g_scale[o] = sc;
    g_shift[o] = bta[o] - mean * sc;
}

// ---------------- BN apply + ReLU -> out[:, :, 15, :] ----------------
__global__ void k_apply(float* __restrict__ outp) {
    int i  = blockIdx.x * blockDim.x + threadIdx.x;
    int r  = i >> 7;
    int cw = i & 127;
    float4 z  = ((const float4*)g_z)[i];
    float4 sc = ((const float4*)g_scale)[cw];
    float4 sh = ((const float4*)g_shift)[cw];
    float4 h;
    h.x = fmaxf(fmaf(z.x, sc.x, sh.x), 0.0f);
    h.y = fmaxf(fmaf(z.y, sc.y, sh.y), 0.0f);
    h.z = fmaxf(fmaf(z.z, sc.z, sh.z), 0.0f);
    h.w = fmaxf(fmaf(z.w, sc.w, sh.w), 0.0f);
    *(float4*)&outp[r*(TT*DD) + 15*DD + cw*4] = h;
}

// ---------------- side stream + events (created pre-main, no allocs in launch) --
namespace {
struct SideStream {
    cudaStream_t s;
    cudaEvent_t evFork, evJoin;
    SideStream() {
        cudaStreamCreateWithFlags(&s, cudaStreamNonBlocking);
        cudaEventCreateWithFlags(&evFork, cudaEventDisableTiming);
        cudaEventCreateWithFlags(&evJoin, cudaEventDisableTiming);
        k_warm<<<1, 32, 0, s>>>();
        cudaStreamSynchronize(s);
    }
};
SideStream g_ss;
}

// ---------------- launcher ----------------
extern "C" void kernel_launch(void* const* d_in, const int* in_sizes, int n_in,
                              void* d_out, int out_size) {
    const float* pf  = (const float*)d_in[0];
    const float* bbx = (const float*)d_in[1];
    const float* w1  = (const float*)d_in[2];
    const float* b1  = (const float*)d_in[3];
    const float* g1  = (const float*)d_in[4];
    const float* be1 = (const float*)d_in[5];
    const float* w2  = (const float*)d_in[6];
    const float* b2  = (const float*)d_in[7];
    const float* g2  = (const float*)d_in[8];
    const float* be2 = (const float*)d_in[9];
    float* out = (float*)d_out;

    static int s_attr_done = 0;
    if (!s_attr_done) {
        cudaFuncSetAttribute(k_gemm_mma, cudaFuncAttributeMaxDynamicSharedMemorySize, GEMM_SMEM);
        s_attr_done = 1;
    }

    // fork: bulk copy of t=0..14 slices runs concurrently on the side stream
    cudaEventRecord(g_ss.evFork, 0);
    cudaStreamWaitEvent(g_ss.s, g_ss.evFork, 0);
    k_copy15<<<dim3(64, 15), 256, 0, g_ss.s>>>((const float4*)pf, (float4*)out);
    cudaEventRecord(g_ss.evJoin, g_ss.s);

    // layer 1
    k_agg<<<dim3(64, 8), 128>>>(pf, bbx, 0);
    k_gemm_mma<<<dim3(64, 4), 256, GEMM_SMEM>>>(w1, b1);
    k_finalize<<<1, 512>>>(g1, be1);

    // layer 2 (BN-apply of layer 1 fused into the aggregation load)
    k_agg<<<dim3(64, 8), 128>>>(nullptr, bbx, 1);
    k_gemm_mma<<<dim3(64, 4), 256, GEMM_SMEM>>>(w2, b2);
    k_finalize<<<1, 512>>>(g2, be2);
    k_apply<<<2048, 256>>>(out);

    // join side stream before the graph/launch completes
    cudaStreamWaitEvent(0, g_ss.evJoin, 0);
}